// round 1
// baseline (speedup 1.0000x reference)
#include <cuda_runtime.h>

// Problem dims (fixed by the dataset)
#define MM 32768   // B*S = 8*4096
#define KK 1024    // D
#define NN 1024    // O
#define RANK 16
#define NBR 5      // 1 shared + 4 tasks

// Scratch for XA = x @ [A_sh; A_tasks]^T  -> [MM][80]
// col layout: cols 0..15 = shared branch, cols 16+t*16+r = task t
__device__ float g_XA[(size_t)MM * 80];

// ---------------------------------------------------------------------------
// Kernel 1: XA[m][c] = sum_d x[m][d] * A_all[c][d]   (skinny GEMM, N=80)
// Block: 128 rows x 80 cols, 256 threads, each thread 8 rows x 5 cols.
// ---------------------------------------------------------------------------
__global__ void __launch_bounds__(256, 1)
xa_kernel(const float* __restrict__ x,
          const float* __restrict__ A_sh,
          const float* __restrict__ A_tasks)
{
    __shared__ float xs[32][132];   // [k][m], padded
    __shared__ float as_[80][36];   // [col][k], padded

    const int m0  = blockIdx.x * 128;
    const int tid = threadIdx.x;
    const int tc  = tid & 15;   // col group: cols tc*5 .. tc*5+4
    const int tr  = tid >> 4;   // row group: rows tr*8 .. tr*8+7

    float acc[8][5];
#pragma unroll
    for (int i = 0; i < 8; ++i)
#pragma unroll
        for (int j = 0; j < 5; ++j) acc[i][j] = 0.f;

    for (int k0 = 0; k0 < KK; k0 += 32) {
        __syncthreads();
        // x tile: 128 rows x 32 k, stored transposed xs[k][m]
#pragma unroll
        for (int c = 0; c < 4; ++c) {
            int i = tid * 4 + c * 1024;
            int row = i >> 5, kq = i & 31;
            float4 v = *(const float4*)(x + (size_t)(m0 + row) * KK + k0 + kq);
            xs[kq + 0][row] = v.x; xs[kq + 1][row] = v.y;
            xs[kq + 2][row] = v.z; xs[kq + 3][row] = v.w;
        }
        // A tile: 80 rows x 32 k, stored as_[col][k]
        for (int i = tid; i < 80 * 32; i += 256) {
            int col = i >> 5, kq = i & 31;
            const float* Ar = (col < 16) ? (A_sh + (size_t)col * KK)
                                         : (A_tasks + (size_t)(col - 16) * KK);
            as_[col][kq] = Ar[k0 + kq];
        }
        __syncthreads();

#pragma unroll 8
        for (int kq = 0; kq < 32; ++kq) {
            float xv[8], av[5];
#pragma unroll
            for (int i = 0; i < 8; ++i) xv[i] = xs[kq][tr * 8 + i];
#pragma unroll
            for (int j = 0; j < 5; ++j) av[j] = as_[tc * 5 + j][kq];
#pragma unroll
            for (int i = 0; i < 8; ++i)
#pragma unroll
                for (int j = 0; j < 5; ++j) acc[i][j] += xv[i] * av[j];
        }
    }

#pragma unroll
    for (int i = 0; i < 8; ++i)
#pragma unroll
        for (int j = 0; j < 5; ++j)
            g_XA[(size_t)(m0 + tr * 8 + i) * 80 + tc * 5 + j] = acc[i][j];
}

// ---------------------------------------------------------------------------
// Kernel 2: fused main GEMM + 5-branch LoRA epilogue.
// Per 128x128 tile:  C = x_tile @ W_tile^T + b           (K = 1024)
//   then for each branch br: out_br = C + s_br * XA_br_tile @ Bbr_tile^T
//   (rank-16 mini K-loop reusing the same smem staging buffers)
// ---------------------------------------------------------------------------
__global__ void __launch_bounds__(256, 1)
main_kernel(const float* __restrict__ x,
            const float* __restrict__ W,
            const float* __restrict__ bias,
            const float* __restrict__ B_sh,
            const float* __restrict__ B_tasks,
            const float* __restrict__ tscale,
            float* __restrict__ out)
{
    __shared__ float As[32][132];   // [k][m]
    __shared__ float Bs[32][132];   // [k][n]

    const int n0  = blockIdx.x * 128;
    const int m0  = blockIdx.y * 128;
    const int tid = threadIdx.x;
    const int tx  = tid & 15;
    const int ty  = tid >> 4;
    const int tm  = ty * 8;
    const int tn  = tx * 8;

    float acc[8][8];
#pragma unroll
    for (int i = 0; i < 8; ++i)
#pragma unroll
        for (int j = 0; j < 8; ++j) acc[i][j] = 0.f;

    // ---- main K loop ----
    for (int k0 = 0; k0 < KK; k0 += 32) {
        __syncthreads();
#pragma unroll
        for (int c = 0; c < 4; ++c) {
            int i = tid * 4 + c * 1024;
            int row = i >> 5, kq = i & 31;
            float4 va = *(const float4*)(x + (size_t)(m0 + row) * KK + k0 + kq);
            As[kq + 0][row] = va.x; As[kq + 1][row] = va.y;
            As[kq + 2][row] = va.z; As[kq + 3][row] = va.w;
            float4 vb = *(const float4*)(W + (size_t)(n0 + row) * KK + k0 + kq);
            Bs[kq + 0][row] = vb.x; Bs[kq + 1][row] = vb.y;
            Bs[kq + 2][row] = vb.z; Bs[kq + 3][row] = vb.w;
        }
        __syncthreads();

#pragma unroll 8
        for (int kq = 0; kq < 32; ++kq) {
            float a[8], bb[8];
            *(float4*)&a[0]  = *(const float4*)&As[kq][tm];
            *(float4*)&a[4]  = *(const float4*)&As[kq][tm + 4];
            *(float4*)&bb[0] = *(const float4*)&Bs[kq][tn];
            *(float4*)&bb[4] = *(const float4*)&Bs[kq][tn + 4];
#pragma unroll
            for (int i = 0; i < 8; ++i)
#pragma unroll
                for (int j = 0; j < 8; ++j) acc[i][j] += a[i] * bb[j];
        }
    }

    // ---- bias (applies to pretrained, i.e. to all 5 outputs) ----
    {
        float bv[8];
#pragma unroll
        for (int j = 0; j < 8; ++j) bv[j] = bias[n0 + tn + j];
#pragma unroll
        for (int i = 0; i < 8; ++i)
#pragma unroll
            for (int j = 0; j < 8; ++j) acc[i][j] += bv[j];
    }

    // ---- per-branch rank-16 epilogue ----
    for (int br = 0; br < NBR; ++br) {
        __syncthreads();
        // XA tile for this branch: 128 rows x 16 -> As[r][m]
#pragma unroll
        for (int c = 0; c < 2; ++c) {
            int i = tid * 4 + c * 1024;
            int row = i >> 4, rr = i & 15;
            float4 v = *(const float4*)(g_XA + (size_t)(m0 + row) * 80 + br * 16 + rr);
            As[rr + 0][row] = v.x; As[rr + 1][row] = v.y;
            As[rr + 2][row] = v.z; As[rr + 3][row] = v.w;
        }
        // B tile for this branch: 128 n-rows x 16 -> Bs[r][n]
        const float* Bp = (br == 0) ? B_sh
                                    : (B_tasks + (size_t)(br - 1) * NN * RANK);
#pragma unroll
        for (int c = 0; c < 2; ++c) {
            int i = tid * 4 + c * 1024;
            int row = i >> 4, rr = i & 15;
            float4 v = *(const float4*)(Bp + (size_t)(n0 + row) * RANK + rr);
            Bs[rr + 0][row] = v.x; Bs[rr + 1][row] = v.y;
            Bs[rr + 2][row] = v.z; Bs[rr + 3][row] = v.w;
        }
        const float s = (br == 0) ? 1.0f : tscale[br - 1];
        __syncthreads();

        float c2[8][8];
#pragma unroll
        for (int i = 0; i < 8; ++i)
#pragma unroll
            for (int j = 0; j < 8; ++j) c2[i][j] = 0.f;

#pragma unroll
        for (int r = 0; r < RANK; ++r) {
            float a[8], bb[8];
            *(float4*)&a[0]  = *(const float4*)&As[r][tm];
            *(float4*)&a[4]  = *(const float4*)&As[r][tm + 4];
            *(float4*)&bb[0] = *(const float4*)&Bs[r][tn];
            *(float4*)&bb[4] = *(const float4*)&Bs[r][tn + 4];
#pragma unroll
            for (int i = 0; i < 8; ++i)
#pragma unroll
                for (int j = 0; j < 8; ++j) c2[i][j] += a[i] * bb[j];
        }

        float* op = out + (size_t)br * MM * NN + (size_t)(m0 + tm) * NN + (n0 + tn);
#pragma unroll
        for (int i = 0; i < 8; ++i) {
            float4 w0, w1;
            w0.x = acc[i][0] + s * c2[i][0];
            w0.y = acc[i][1] + s * c2[i][1];
            w0.z = acc[i][2] + s * c2[i][2];
            w0.w = acc[i][3] + s * c2[i][3];
            w1.x = acc[i][4] + s * c2[i][4];
            w1.y = acc[i][5] + s * c2[i][5];
            w1.z = acc[i][6] + s * c2[i][6];
            w1.w = acc[i][7] + s * c2[i][7];
            *(float4*)(op + (size_t)i * NN)     = w0;
            *(float4*)(op + (size_t)i * NN + 4) = w1;
        }
    }
}

// ---------------------------------------------------------------------------
extern "C" void kernel_launch(void* const* d_in, const int* in_sizes, int n_in,
                              void* d_out, int out_size)
{
    const float* x        = (const float*)d_in[0];
    const float* W        = (const float*)d_in[1];
    const float* b        = (const float*)d_in[2];
    const float* A_sh     = (const float*)d_in[3];
    const float* B_sh     = (const float*)d_in[4];
    const float* A_tasks  = (const float*)d_in[5];
    const float* B_tasks  = (const float*)d_in[6];
    const float* tscale   = (const float*)d_in[7];
    float* out            = (float*)d_out;

    xa_kernel<<<MM / 128, 256>>>(x, A_sh, A_tasks);

    dim3 grid(NN / 128, MM / 128);
    main_kernel<<<grid, 256>>>(x, W, b, B_sh, B_tasks, tscale, out);
}